// round 5
// baseline (speedup 1.0000x reference)
#include <cuda_runtime.h>
#include <mma.h>
#include <math.h>
using namespace nvcuda;

#define NMAX 50000
#define EMAX 800000
#define NP   50048   // 391*128, padded rows so wmma stores need no guard
#define SB   512     // scan block size

// ---------------- scratch (device globals; no allocation allowed) ------------
__device__ float d_h1[NP * 256];     // layer1 transformed features (padded)
__device__ float d_al1[NMAX * 4];
__device__ float d_ar1[NMAX * 4];
__device__ float d_g1[NMAX];
__device__ float d_x2[NMAX * 256];   // elu(normalized aggregate) = GEMM2 input
__device__ float d_h2[NP * 64];      // layer2 transformed features (padded)
__device__ float d_al2[NMAX];
__device__ float d_ar2[NMAX];
__device__ float d_g2[NMAX];
// CSR (edges sorted by destination)
__device__ int   d_deg[NMAX];
__device__ int   d_cur[NMAX];
__device__ int   d_rs[NMAX + 1];
__device__ int   d_bt[(NMAX + SB - 1) / SB];
__device__ int   d_srcs[EMAX];

__device__ __forceinline__ float elu_f(float v) {
    return v > 0.f ? v : (__expf(v) - 1.0f);
}

// ---------------- split-TF32 tensor-core GEMM: C[N,M] = A[N,K] @ B[K,M] -------
// a = a_hi + a_lo (each tf32); acc += a_hi*b_hi + a_hi*b_lo + a_lo*b_hi (fp32).
// Dropped a_lo*b_lo ~ 2^-22 relative -> fp32-level accuracy on tensor cores.
// Block tile 128x64, BK=32, 256 thr = 8 warps (4x2), warp tile 32x32.
__global__ __launch_bounds__(256) void gemm_tf32x3(
        const float* __restrict__ A, const float* __restrict__ B,
        float* __restrict__ C, int N, int K, int M) {
    __shared__ float As[128][40];
    __shared__ float Bs[32][72];
    int tid = threadIdx.x;
    int wid = tid >> 5;
    int wm = wid >> 1, wn = wid & 1;
    int row0 = blockIdx.y * 128, col0 = blockIdx.x * 64;

    wmma::fragment<wmma::accumulator, 16, 16, 8, float> acc[2][2];
    #pragma unroll
    for (int i = 0; i < 2; i++)
        #pragma unroll
        for (int j = 0; j < 2; j++)
            wmma::fill_fragment(acc[i][j], 0.0f);

    for (int k0 = 0; k0 < K; k0 += 32) {
        #pragma unroll
        for (int i = 0; i < 4; i++) {       // A tile: 128x32 = 1024 float4
            int f = tid + i * 256;
            int r = f >> 3, c = (f & 7) * 4;
            int row = row0 + r;
            float4 v = make_float4(0.f, 0.f, 0.f, 0.f);
            if (row < N) v = *(const float4*)&A[(size_t)row * K + k0 + c];
            *(float4*)&As[r][c] = v;
        }
        #pragma unroll
        for (int i = 0; i < 2; i++) {       // B tile: 32x64 = 512 float4
            int f = tid + i * 256;
            int r = f >> 4, c = (f & 15) * 4;
            *(float4*)&Bs[r][c] = *(const float4*)&B[(size_t)(k0 + r) * M + col0 + c];
        }
        __syncthreads();

        #pragma unroll
        for (int kk = 0; kk < 4; kk++) {
            wmma::fragment<wmma::matrix_a, 16, 16, 8, wmma::precision::tf32, wmma::row_major> ahi[2], alo[2];
            wmma::fragment<wmma::matrix_b, 16, 16, 8, wmma::precision::tf32, wmma::row_major> bhi[2], blo[2];
            #pragma unroll
            for (int i = 0; i < 2; i++) {
                wmma::load_matrix_sync(ahi[i], &As[wm * 32 + i * 16][kk * 8], 40);
                #pragma unroll
                for (int t = 0; t < ahi[i].num_elements; t++) {
                    float full = ahi[i].x[t];
                    float hi = wmma::__float_to_tf32(full);
                    ahi[i].x[t] = hi;
                    alo[i].x[t] = wmma::__float_to_tf32(full - hi);
                }
            }
            #pragma unroll
            for (int j = 0; j < 2; j++) {
                wmma::load_matrix_sync(bhi[j], &Bs[kk * 8][wn * 32 + j * 16], 72);
                #pragma unroll
                for (int t = 0; t < bhi[j].num_elements; t++) {
                    float full = bhi[j].x[t];
                    float hi = wmma::__float_to_tf32(full);
                    bhi[j].x[t] = hi;
                    blo[j].x[t] = wmma::__float_to_tf32(full - hi);
                }
            }
            #pragma unroll
            for (int i = 0; i < 2; i++)
                #pragma unroll
                for (int j = 0; j < 2; j++) {
                    wmma::mma_sync(acc[i][j], alo[i], bhi[j], acc[i][j]);
                    wmma::mma_sync(acc[i][j], ahi[i], blo[j], acc[i][j]);
                    wmma::mma_sync(acc[i][j], ahi[i], bhi[j], acc[i][j]);
                }
        }
        __syncthreads();
    }
    #pragma unroll
    for (int i = 0; i < 2; i++)
        #pragma unroll
        for (int j = 0; j < 2; j++)
            wmma::store_matrix_sync(&C[(size_t)(row0 + wm * 32 + i * 16) * M +
                                       col0 + wn * 32 + j * 16],
                                    acc[i][j], M, wmma::mem_row_major);
}

// ---------------- CSR build ---------------------------------------------------
__global__ void k_count(const int* __restrict__ dst, int E) {
    int e = blockIdx.x * blockDim.x + threadIdx.x;
    if (e < E) atomicAdd(&d_deg[dst[e]], 1);
}
__global__ void k_scan1(int N) {
    __shared__ int sm[SB];
    int i = blockIdx.x * SB + threadIdx.x;
    int v = (i < N) ? d_deg[i] : 0;
    sm[threadIdx.x] = v;
    __syncthreads();
    #pragma unroll
    for (int off = 1; off < SB; off <<= 1) {
        int t = (threadIdx.x >= off) ? sm[threadIdx.x - off] : 0;
        __syncthreads();
        sm[threadIdx.x] += t;
        __syncthreads();
    }
    if (i < N) d_rs[i] = sm[threadIdx.x] - v;
    if (threadIdx.x == SB - 1) d_bt[blockIdx.x] = sm[SB - 1];
}
__global__ void k_scan2(int nb) {
    if (threadIdx.x == 0) {
        int run = 0;
        for (int b = 0; b < nb; b++) { int t = d_bt[b]; d_bt[b] = run; run += t; }
    }
}
__global__ void k_scan3(int N, int E) {
    int i = blockIdx.x * SB + threadIdx.x;
    if (i < N) d_rs[i] += d_bt[blockIdx.x];
    if (i == 0) d_rs[N] = E;
}
__global__ void k_scatter(const int* __restrict__ src, const int* __restrict__ dst, int E) {
    int e = blockIdx.x * blockDim.x + threadIdx.x;
    if (e >= E) return;
    int d = dst[e];
    int pos = d_rs[d] + atomicAdd(&d_cur[d], 1);
    d_srcs[pos] = src[e];
}

// ---------------- layer1 node prep: al/ar dot-products + guidance -------------
__global__ void node_prep1(const float* __restrict__ x,
                           const float* __restrict__ attl,
                           const float* __restrict__ attr, int N) {
    int w = (blockIdx.x * blockDim.x + threadIdx.x) >> 5;
    int lane = threadIdx.x & 31;
    if (w >= N) return;
    const float* hrow = &d_h1[(size_t)w * 256];
    float aL[4] = {0.f, 0.f, 0.f, 0.f}, aR[4] = {0.f, 0.f, 0.f, 0.f};
    #pragma unroll
    for (int i = 0; i < 8; i++) {
        int idx = lane + i * 32;
        float hv = hrow[idx];
        int h = idx >> 6;
        aL[h] += hv * attl[idx];
        aR[h] += hv * attr[idx];
    }
    #pragma unroll
    for (int h = 0; h < 4; h++) {
        #pragma unroll
        for (int off = 16; off; off >>= 1) {
            aL[h] += __shfl_xor_sync(0xffffffffu, aL[h], off);
            aR[h] += __shfl_xor_sync(0xffffffffu, aR[h], off);
        }
    }
    if (lane == 0) {
        #pragma unroll
        for (int h = 0; h < 4; h++) {
            d_al1[w * 4 + h] = aL[h];
            d_ar1[w * 4 + h] = aR[h];
        }
        // L1-normalization constant of rw cancels in segment softmax -> drop it
        d_g1[w] = -0.1f * logf(fabsf(x[(size_t)w * 128 + 127]) + 1e-6f);
    }
}

// ---------------- layer1 CSR aggregation: warp per dst node -------------------
__global__ void agg1_csr(int N) {
    int n = (blockIdx.x * blockDim.x + threadIdx.x) >> 5;
    int lane = threadIdx.x & 31;
    if (n >= N) return;
    int beg = d_rs[n], end = d_rs[n + 1];
    float alh = (lane < 4) ? d_al1[n * 4 + lane] : 0.f;
    float4 accA = make_float4(0.f, 0.f, 0.f, 0.f);
    float4 accB = make_float4(0.f, 0.f, 0.f, 0.f);
    float wsum = 0.f;
    for (int p = beg; p < end; p++) {
        int s = d_srcs[p];
        float ex = 0.f;
        if (lane < 4) {
            float v = alh + d_ar1[s * 4 + lane];
            v = v > 0.f ? v : 0.01f * v;        // leaky relu
            v += d_g1[s];                       // guidance (shift-safe softmax)
            ex = __expf(v);
            wsum += ex;
        }
        float w0 = __shfl_sync(0xffffffffu, ex, 0);
        float w1 = __shfl_sync(0xffffffffu, ex, 1);
        float w2 = __shfl_sync(0xffffffffu, ex, 2);
        float w3 = __shfl_sync(0xffffffffu, ex, 3);
        float wa = (lane < 16) ? w0 : w1;
        float wb = (lane < 16) ? w2 : w3;
        const float4* hs = (const float4*)&d_h1[(size_t)s * 256];
        float4 a = hs[lane];
        float4 b = hs[lane + 32];
        accA.x += a.x * wa; accA.y += a.y * wa; accA.z += a.z * wa; accA.w += a.w * wa;
        accB.x += b.x * wb; accB.y += b.y * wb; accB.z += b.z * wb; accB.w += b.w * wb;
    }
    float s0 = __shfl_sync(0xffffffffu, wsum, 0);
    float s1 = __shfl_sync(0xffffffffu, wsum, 1);
    float s2 = __shfl_sync(0xffffffffu, wsum, 2);
    float s3 = __shfl_sync(0xffffffffu, wsum, 3);
    float inva = 1.f / (((lane < 16) ? s0 : s1) + 1e-16f);
    float invb = 1.f / (((lane < 16) ? s2 : s3) + 1e-16f);
    accA.x = elu_f(accA.x * inva); accA.y = elu_f(accA.y * inva);
    accA.z = elu_f(accA.z * inva); accA.w = elu_f(accA.w * inva);
    accB.x = elu_f(accB.x * invb); accB.y = elu_f(accB.y * invb);
    accB.z = elu_f(accB.z * invb); accB.w = elu_f(accB.w * invb);
    float* xr = &d_x2[(size_t)n * 256];
    *(float4*)&xr[lane * 4] = accA;
    *(float4*)&xr[128 + lane * 4] = accB;
    if (lane == 31)
        d_g2[n] = -0.1f * logf(fabsf(accB.w) + 1e-6f);
}

// ---------------- layer2 node prep --------------------------------------------
__global__ void node_prep2(const float* __restrict__ attl,
                           const float* __restrict__ attr, int N) {
    int w = (blockIdx.x * blockDim.x + threadIdx.x) >> 5;
    int lane = threadIdx.x & 31;
    if (w >= N) return;
    float aL = 0.f, aR = 0.f;
    #pragma unroll
    for (int i = 0; i < 2; i++) {
        int idx = lane + i * 32;
        float hv = d_h2[(size_t)w * 64 + idx];
        aL += hv * attl[idx];
        aR += hv * attr[idx];
    }
    #pragma unroll
    for (int off = 16; off; off >>= 1) {
        aL += __shfl_xor_sync(0xffffffffu, aL, off);
        aR += __shfl_xor_sync(0xffffffffu, aR, off);
    }
    if (lane == 0) { d_al2[w] = aL; d_ar2[w] = aR; }
}

// ---------------- layer2 CSR aggregation + normalize + ELU + final FC ---------
__global__ void agg2_csr(const float* __restrict__ fcw, const float* __restrict__ fcb,
                         float* __restrict__ out, int N) {
    int n = (blockIdx.x * blockDim.x + threadIdx.x) >> 5;
    int lane = threadIdx.x & 31;
    if (n >= N) return;
    int beg = d_rs[n], end = d_rs[n + 1];
    float aln = d_al2[n];
    float2 acc = make_float2(0.f, 0.f);
    float wsum = 0.f;
    for (int p = beg; p < end; p++) {
        int s = d_srcs[p];
        float ex = 0.f;
        if (lane == 0) {
            float v = aln + d_ar2[s];
            v = v > 0.f ? v : 0.01f * v;
            v += d_g2[s];
            ex = __expf(v);
            wsum += ex;
        }
        ex = __shfl_sync(0xffffffffu, ex, 0);
        float2 hv = ((const float2*)&d_h2[(size_t)s * 64])[lane];
        acc.x += hv.x * ex;
        acc.y += hv.y * ex;
    }
    wsum = __shfl_sync(0xffffffffu, wsum, 0);
    float inv = 1.f / (wsum + 1e-16f);
    float v0 = elu_f(acc.x * inv);
    float v1 = elu_f(acc.y * inv);
    float dot = v0 * fcw[2 * lane] + v1 * fcw[2 * lane + 1];
    #pragma unroll
    for (int off = 16; off; off >>= 1)
        dot += __shfl_xor_sync(0xffffffffu, dot, off);
    if (lane == 0) out[n] = dot + fcb[0];
}

// ---------------- host launcher ----------------------------------------------
extern "C" void kernel_launch(void* const* d_in, const int* in_sizes, int n_in,
                              void* d_out, int out_size) {
    const float* x     = (const float*)d_in[0];
    const int*   ei    = (const int*)d_in[1];
    const float* W1    = (const float*)d_in[2];
    const float* attl1 = (const float*)d_in[3];
    const float* attr1 = (const float*)d_in[4];
    const float* W2    = (const float*)d_in[5];
    const float* attl2 = (const float*)d_in[6];
    const float* attr2 = (const float*)d_in[7];
    const float* fcw   = (const float*)d_in[8];
    const float* fcb   = (const float*)d_in[9];
    float* out = (float*)d_out;

    int N = in_sizes[0] / 128;
    int E = in_sizes[1] / 2;
    const int* src = ei;
    const int* dst = ei + E;

    void *ph1, *ph2, *px2, *pdeg, *pcur;
    cudaGetSymbolAddress(&ph1, d_h1);
    cudaGetSymbolAddress(&ph2, d_h2);
    cudaGetSymbolAddress(&px2, d_x2);
    cudaGetSymbolAddress(&pdeg, d_deg);
    cudaGetSymbolAddress(&pcur, d_cur);

    const int TB = 256;
    int gy = (N + 127) / 128;
    int nb = (N + SB - 1) / SB;

    // ---- CSR build (dst-sorted edges) ----
    cudaMemsetAsync(pdeg, 0, sizeof(int) * (size_t)N, 0);
    cudaMemsetAsync(pcur, 0, sizeof(int) * (size_t)N, 0);
    k_count<<<(E + TB - 1) / TB, TB>>>(dst, E);
    k_scan1<<<nb, SB>>>(N);
    k_scan2<<<1, 32>>>(nb);
    k_scan3<<<nb, SB>>>(N, E);
    k_scatter<<<(E + TB - 1) / TB, TB>>>(src, dst, E);

    // ---- layer 1 ----
    gemm_tf32x3<<<dim3(4, gy), TB>>>(x, W1, (float*)ph1, N, 128, 256);
    node_prep1<<<(N * 32 + TB - 1) / TB, TB>>>(x, attl1, attr1, N);
    agg1_csr<<<(N * 32 + TB - 1) / TB, TB>>>(N);

    // ---- layer 2 ----
    gemm_tf32x3<<<dim3(1, gy), TB>>>((const float*)px2, W2, (float*)ph2, N, 256, 64);
    node_prep2<<<(N * 32 + TB - 1) / TB, TB>>>(attl2, attr2, N);
    agg2_csr<<<(N * 32 + TB - 1) / TB, TB>>>(fcw, fcb, out, N);
}